// round 4
// baseline (speedup 1.0000x reference)
#include <cuda_runtime.h>

#define EPS_F 1e-9f
#define DIM   128
#define NTHR  256
#define EBLK  1184            // 8 blocks/SM * 148 SMs, all resident
#define NBA_MAX 1024
#define MAX_NODES 200000

// Scratch (no allocations allowed)
__device__ float2       g_tab[MAX_NODES];
__device__ double       g_part_prox[EBLK];
__device__ double       g_part_comp[NBA_MAX];
__device__ unsigned int g_done = 0;

// ---------------------------------------------------------------------------
__device__ __forceinline__ double block_reduce_double(double v, double* s) {
    int lane = threadIdx.x & 31;
    int wid  = threadIdx.x >> 5;
    #pragma unroll
    for (int o = 16; o; o >>= 1) v += __shfl_down_sync(0xffffffffu, v, o);
    if (lane == 0) s[wid] = v;
    __syncthreads();
    v = (threadIdx.x < (NTHR >> 5)) ? s[threadIdx.x] : 0.0;
    if (wid == 0) {
        #pragma unroll
        for (int o = 16; o; o >>= 1) v += __shfl_down_sync(0xffffffffu, v, o);
    }
    return v;  // valid on thread 0
}

// Exact fp32 rounding-order replication of the reference (no FMA contraction).
__device__ __forceinline__ float ref_inner(float ax, float ay, float bx, float by) {
    float u = __fadd_rn(__fmul_rn(ax, bx), __fmul_rn(ay, by));
    return __fadd_rn(-u, 1.0f);
}

__device__ __forceinline__ float ref_safe_div(float num, float den) {
    float sgn  = (den > 0.0f) ? 1.0f : ((den < 0.0f) ? -1.0f : 0.0f);
    float safe = __fmul_rn(fmaxf(fabsf(den), EPS_F), sgn);
    return __fdiv_rn(num, safe);
}

__device__ __forceinline__ float edge_quad(float2 a, float2 b) {
    float aa  = ref_inner(a.x, a.y, a.x, a.y);
    float bb  = ref_inner(b.x, b.y, b.x, b.y);
    float ab  = ref_inner(a.x, a.y, b.x, b.y);
    float den = __fmul_rn(aa, bb);
    float num = __fsub_rn(__fmul_rn(ab, ab), den);
    return ref_safe_div(num, den);
}

// ---------------------------------------------------------------------------
// Kernel A: build compact (x,y) table + per-block compactness partials.
__global__ __launch_bounds__(NTHR)
void node_kernel(const float* __restrict__ z, int n_nodes) {
    __shared__ double s_red[32];
    int i = blockIdx.x * NTHR + threadIdx.x;
    double comp = 0.0;
    if (i < n_nodes) {
        float2 xy = *reinterpret_cast<const float2*>(z + (size_t)i * DIM);
        g_tab[i] = xy;
        float aa  = ref_inner(xy.x, xy.y, xy.x, xy.y);
        float num = __fsub_rn(1.0f, aa);   // ab*ab - aa*bb with ab=bb=1
        comp = (double)ref_safe_div(num, aa);
    }
    double bsum = block_reduce_double(comp, s_red);
    if (threadIdx.x == 0) g_part_comp[blockIdx.x] = bsum;
}

// ---------------------------------------------------------------------------
// Kernel B: proximity over all edges. 32-reg budget -> 8 blocks/SM resident.
__global__ __launch_bounds__(NTHR, 8)
void edge_kernel(const int* __restrict__ src,
                 const int* __restrict__ dst,
                 long long n_edges, int n_nodes, int n_comp_blocks,
                 float* __restrict__ out) {
    __shared__ double s_red[32];
    __shared__ double s_pc[2];
    __shared__ unsigned int s_last;

    long long tid    = (long long)blockIdx.x * NTHR + threadIdx.x;
    long long stride = (long long)gridDim.x * NTHR;

    double prox = 0.0;
    long long n2 = n_edges >> 1;
    const int2* s2 = reinterpret_cast<const int2*>(src);
    const int2* d2 = reinterpret_cast<const int2*>(dst);
    #pragma unroll 1
    for (long long i = tid; i < n2; i += stride) {
        int2 s = s2[i];
        int2 d = d2[i];
        float2 a0 = g_tab[s.x], b0 = g_tab[d.x];
        float2 a1 = g_tab[s.y], b1 = g_tab[d.y];
        float q0 = edge_quad(a0, b0);
        float q1 = edge_quad(a1, b1);
        prox += (double)__fadd_rn(q0, q1);   // one DADD per 2 edges
    }
    for (long long e = (n2 << 1) + tid; e < n_edges; e += stride) {
        prox += (double)edge_quad(g_tab[src[e]], g_tab[dst[e]]);
    }

    double bp = block_reduce_double(prox, s_red);
    if (threadIdx.x == 0) {
        g_part_prox[blockIdx.x] = bp;
        __threadfence();
        unsigned int t = atomicAdd(&g_done, 1u);
        s_last = (t == gridDim.x - 1) ? 1u : 0u;
    }
    __syncthreads();

    if (s_last) {
        double p = 0.0, c = 0.0;
        for (int i = threadIdx.x; i < gridDim.x; i += NTHR) p += g_part_prox[i];
        for (int i = threadIdx.x; i < n_comp_blocks; i += NTHR) c += g_part_comp[i];
        p = block_reduce_double(p, s_red);
        __syncthreads();
        c = block_reduce_double(c, s_red);
        if (threadIdx.x == 0) { s_pc[0] = p; s_pc[1] = c; }
        __syncthreads();

        if (threadIdx.x < 32) {
            int n_sp = (int)((n_edges < 10) ? n_edges : 10);
            double q = 0.0;
            if (threadIdx.x < n_sp) {
                float2 a = g_tab[src[threadIdx.x]];
                float2 b = g_tab[dst[threadIdx.x]];
                // lines: cross([x,y,1],[0,0,1]) = (y, -x, 0); time = 0
                float aa  = -__fadd_rn(__fmul_rn(a.y, a.y), __fmul_rn(a.x, a.x));
                float bb  = -__fadd_rn(__fmul_rn(b.y, b.y), __fmul_rn(b.x, b.x));
                float ab  = -__fadd_rn(__fmul_rn(a.y, b.y), __fmul_rn(a.x, b.x));
                float den = __fmul_rn(aa, bb);
                float num = __fsub_rn(__fmul_rn(ab, ab), den);
                q = (double)ref_safe_div(num, den);
            }
            #pragma unroll
            for (int o = 16; o; o >>= 1) q += __shfl_down_sync(0xffffffffu, q, o);
            if (threadIdx.x == 0) {
                double prox_m = s_pc[0] / (double)n_edges;
                double comp_m = s_pc[1] / (double)n_nodes;
                double spr_m  = q / (double)n_sp;
                out[0] = (float)((prox_m + comp_m) + 0.1 * spr_m);
                g_done = 0u;   // reset for next graph replay
            }
        }
    }
}

// ---------------------------------------------------------------------------
extern "C" void kernel_launch(void* const* d_in, const int* in_sizes, int n_in,
                              void* d_out, int out_size) {
    const float* z  = (const float*)d_in[0];
    const int*   ei = (const int*)d_in[1];

    int       n_nodes = in_sizes[0] / DIM;
    long long n_edges = (long long)in_sizes[1] / 2;
    const int* src = ei;
    const int* dst = ei + n_edges;

    int nba = (n_nodes + NTHR - 1) / NTHR;
    node_kernel<<<nba, NTHR>>>(z, n_nodes);
    edge_kernel<<<EBLK, NTHR>>>(src, dst, n_edges, n_nodes, nba, (float*)d_out);
}

// round 5
// speedup vs baseline: 1.0527x; 1.0527x over previous
#include <cuda_runtime.h>

#define EPS_F 1e-9f
#define DIM   128
#define NTHR  256
#define NBLK  888             // 6 blocks/SM * 148 SMs -> all resident (safe grid sync)
#define MAX_NODES 200000

// Scratch (no allocations allowed)
__device__ float2       g_tab[MAX_NODES];
__device__ double       g_part_prox[NBLK];
__device__ double       g_part_comp[NBLK];
__device__ unsigned int g_sync = 0;   // phase-1 barrier
__device__ unsigned int g_done = 0;   // completion ticket

// ---------------------------------------------------------------------------
__device__ __forceinline__ double block_reduce_double(double v, double* s) {
    int lane = threadIdx.x & 31;
    int wid  = threadIdx.x >> 5;
    #pragma unroll
    for (int o = 16; o; o >>= 1) v += __shfl_down_sync(0xffffffffu, v, o);
    if (lane == 0) s[wid] = v;
    __syncthreads();
    v = (threadIdx.x < (NTHR >> 5)) ? s[threadIdx.x] : 0.0;
    if (wid == 0) {
        #pragma unroll
        for (int o = 16; o; o >>= 1) v += __shfl_down_sync(0xffffffffu, v, o);
    }
    return v;  // valid on thread 0
}

// Exact fp32 rounding-order replication of the reference (no FMA contraction).
__device__ __forceinline__ float ref_inner(float ax, float ay, float bx, float by) {
    float u = __fadd_rn(__fmul_rn(ax, bx), __fmul_rn(ay, by));
    return __fadd_rn(-u, 1.0f);
}

__device__ __forceinline__ float ref_safe_div(float num, float den) {
    float sgn  = (den > 0.0f) ? 1.0f : ((den < 0.0f) ? -1.0f : 0.0f);
    float safe = __fmul_rn(fmaxf(fabsf(den), EPS_F), sgn);
    return __fdiv_rn(num, safe);
}

__device__ __forceinline__ float edge_quad(float2 a, float2 b) {
    float aa  = ref_inner(a.x, a.y, a.x, a.y);
    float bb  = ref_inner(b.x, b.y, b.x, b.y);
    float ab  = ref_inner(a.x, a.y, b.x, b.y);
    float den = __fmul_rn(aa, bb);
    float num = __fsub_rn(__fmul_rn(ab, ab), den);
    return ref_safe_div(num, den);
}

// ---------------------------------------------------------------------------
__global__ __launch_bounds__(NTHR, 6)
void fused_kernel(const float* __restrict__ z,
                  const int*  __restrict__ src,
                  const int*  __restrict__ dst,
                  long long n_edges, int n_nodes,
                  float* __restrict__ out) {
    __shared__ double s_red[32];
    __shared__ double s_pc[2];
    __shared__ unsigned int s_last;

    long long tid    = (long long)blockIdx.x * NTHR + threadIdx.x;
    long long stride = (long long)NBLK * NTHR;

    // ---- phase 1: build compact table + compactness partial --------------
    double comp = 0.0;
    for (long long i = tid; i < n_nodes; i += stride) {
        float2 xy = *reinterpret_cast<const float2*>(z + i * DIM);
        g_tab[i] = xy;
        float aa  = ref_inner(xy.x, xy.y, xy.x, xy.y);
        float num = __fsub_rn(1.0f, aa);   // ab*ab - aa*bb with ab=bb=1
        comp += (double)ref_safe_div(num, aa);
    }
    double bc = block_reduce_double(comp, s_red);
    if (threadIdx.x == 0) g_part_comp[blockIdx.x] = bc;

    // ---- grid barrier (all blocks resident by construction) --------------
    __threadfence();
    __syncthreads();
    if (threadIdx.x == 0) {
        atomicAdd(&g_sync, 1u);
        volatile unsigned int* vs = &g_sync;
        while (*vs < (unsigned int)NBLK) { }
    }
    __syncthreads();
    __threadfence();

    // ---- phase 2: proximity over all edges (4-edge batches) --------------
    double prox = 0.0;
    long long n4 = n_edges >> 2;
    const int4* s4 = reinterpret_cast<const int4*>(src);
    const int4* d4 = reinterpret_cast<const int4*>(dst);
    #pragma unroll 1
    for (long long i = tid; i < n4; i += stride) {
        int4 s = s4[i];
        int4 d = d4[i];
        float2 a0 = g_tab[s.x], b0 = g_tab[d.x];
        float2 a1 = g_tab[s.y], b1 = g_tab[d.y];
        float2 a2 = g_tab[s.z], b2 = g_tab[d.z];
        float2 a3 = g_tab[s.w], b3 = g_tab[d.w];
        float q0 = edge_quad(a0, b0);
        float q1 = edge_quad(a1, b1);
        float q2 = edge_quad(a2, b2);
        float q3 = edge_quad(a3, b3);
        prox += (double)__fadd_rn(__fadd_rn(q0, q1), __fadd_rn(q2, q3));
    }
    for (long long e = (n4 << 2) + tid; e < n_edges; e += stride) {
        prox += (double)edge_quad(g_tab[src[e]], g_tab[dst[e]]);
    }

    double bp = block_reduce_double(prox, s_red);
    if (threadIdx.x == 0) {
        g_part_prox[blockIdx.x] = bp;
        __threadfence();
        unsigned int t = atomicAdd(&g_done, 1u);
        s_last = (t == NBLK - 1) ? 1u : 0u;
    }
    __syncthreads();

    // ---- phase 3: last block finishes ------------------------------------
    if (s_last) {
        double p = 0.0, c = 0.0;
        for (int i = threadIdx.x; i < NBLK; i += NTHR) {
            p += g_part_prox[i];
            c += g_part_comp[i];
        }
        p = block_reduce_double(p, s_red);
        __syncthreads();
        c = block_reduce_double(c, s_red);
        if (threadIdx.x == 0) { s_pc[0] = p; s_pc[1] = c; }
        __syncthreads();

        if (threadIdx.x < 32) {
            int n_sp = (int)((n_edges < 10) ? n_edges : 10);
            double q = 0.0;
            if (threadIdx.x < n_sp) {
                float2 a = g_tab[src[threadIdx.x]];
                float2 b = g_tab[dst[threadIdx.x]];
                // lines: cross([x,y,1],[0,0,1]) = (y, -x, 0); time = 0
                float aa  = -__fadd_rn(__fmul_rn(a.y, a.y), __fmul_rn(a.x, a.x));
                float bb  = -__fadd_rn(__fmul_rn(b.y, b.y), __fmul_rn(b.x, b.x));
                float ab  = -__fadd_rn(__fmul_rn(a.y, b.y), __fmul_rn(a.x, b.x));
                float den = __fmul_rn(aa, bb);
                float num = __fsub_rn(__fmul_rn(ab, ab), den);
                q = (double)ref_safe_div(num, den);
            }
            #pragma unroll
            for (int o = 16; o; o >>= 1) q += __shfl_down_sync(0xffffffffu, q, o);
            if (threadIdx.x == 0) {
                double prox_m = s_pc[0] / (double)n_edges;
                double comp_m = s_pc[1] / (double)n_nodes;
                double spr_m  = q / (double)n_sp;
                out[0] = (float)((prox_m + comp_m) + 0.1 * spr_m);
                g_done = 0u;   // reset for next graph replay
                g_sync = 0u;
            }
        }
    }
}

// ---------------------------------------------------------------------------
extern "C" void kernel_launch(void* const* d_in, const int* in_sizes, int n_in,
                              void* d_out, int out_size) {
    const float* z  = (const float*)d_in[0];
    const int*   ei = (const int*)d_in[1];

    int       n_nodes = in_sizes[0] / DIM;
    long long n_edges = (long long)in_sizes[1] / 2;
    const int* src = ei;
    const int* dst = ei + n_edges;

    fused_kernel<<<NBLK, NTHR>>>(z, src, dst, n_edges, n_nodes, (float*)d_out);
}

// round 6
// speedup vs baseline: 1.0784x; 1.0244x over previous
#include <cuda_runtime.h>

#define EPS_F 1e-9f
#define DIM   128
#define NTHR  256
#define EBLK  1184
#define NBA_MAX 1024
#define MAX_NODES 200000

// Scratch (no allocations allowed)
__device__ float2       g_tab[MAX_NODES];
__device__ double       g_part_prox[EBLK];
__device__ double       g_part_comp[NBA_MAX];
__device__ unsigned int g_done = 0;

// ---------------------------------------------------------------------------
__device__ __forceinline__ double block_reduce_double(double v, double* s) {
    int lane = threadIdx.x & 31;
    int wid  = threadIdx.x >> 5;
    #pragma unroll
    for (int o = 16; o; o >>= 1) v += __shfl_down_sync(0xffffffffu, v, o);
    if (lane == 0) s[wid] = v;
    __syncthreads();
    v = (threadIdx.x < (NTHR >> 5)) ? s[threadIdx.x] : 0.0;
    if (wid == 0) {
        #pragma unroll
        for (int o = 16; o; o >>= 1) v += __shfl_down_sync(0xffffffffu, v, o);
    }
    return v;  // valid on thread 0
}

// Exact fp32 rounding-order replication of the reference (no FMA contraction).
__device__ __forceinline__ float ref_inner(float ax, float ay, float bx, float by) {
    float u = __fadd_rn(__fmul_rn(ax, bx), __fmul_rn(ay, by));
    return __fadd_rn(-u, 1.0f);
}

__device__ __forceinline__ float ref_safe_div(float num, float den) {
    float sgn  = (den > 0.0f) ? 1.0f : ((den < 0.0f) ? -1.0f : 0.0f);
    float safe = __fmul_rn(fmaxf(fabsf(den), EPS_F), sgn);
    return __fdiv_rn(num, safe);
}

__device__ __forceinline__ float edge_quad(float2 a, float2 b) {
    float aa  = ref_inner(a.x, a.y, a.x, a.y);
    float bb  = ref_inner(b.x, b.y, b.x, b.y);
    float ab  = ref_inner(a.x, a.y, b.x, b.y);
    float den = __fmul_rn(aa, bb);
    float num = __fsub_rn(__fmul_rn(ab, ab), den);
    return ref_safe_div(num, den);
}

// ---------------------------------------------------------------------------
// Kernel A: build compact (x,y) table + per-block compactness partials.
__global__ __launch_bounds__(NTHR)
void node_kernel(const float* __restrict__ z, int n_nodes) {
    __shared__ double s_red[32];
    int i = blockIdx.x * NTHR + threadIdx.x;
    double comp = 0.0;
    if (i < n_nodes) {
        float2 xy = *reinterpret_cast<const float2*>(z + (size_t)i * DIM);
        g_tab[i] = xy;
        float aa  = ref_inner(xy.x, xy.y, xy.x, xy.y);
        float num = __fsub_rn(1.0f, aa);   // ab*ab - aa*bb with ab=bb=1
        comp = (double)ref_safe_div(num, aa);
    }
    double bsum = block_reduce_double(comp, s_red);
    if (threadIdx.x == 0) g_part_comp[blockIdx.x] = bsum;
}

// ---------------------------------------------------------------------------
// Kernel B: proximity over edges. 8-edge batches for deep MLP; streaming
// index loads (__ldcs) keep the table L1-resident; table via __ldg.
__global__ __launch_bounds__(NTHR, 4)
void edge_kernel(const int* __restrict__ src,
                 const int* __restrict__ dst,
                 long long n_edges, int n_nodes, int n_comp_blocks,
                 float* __restrict__ out) {
    __shared__ double s_red[32];
    __shared__ double s_pc[2];
    __shared__ unsigned int s_last;

    long long tid    = (long long)blockIdx.x * NTHR + threadIdx.x;
    long long stride = (long long)gridDim.x * NTHR;

    double prox = 0.0;
    long long n8 = n_edges >> 3;
    const int4* s4 = reinterpret_cast<const int4*>(src);
    const int4* d4 = reinterpret_cast<const int4*>(dst);
    #pragma unroll 1
    for (long long i = tid; i < n8; i += stride) {
        int4 sa = __ldcs(s4 + 2 * i);
        int4 sb = __ldcs(s4 + 2 * i + 1);
        int4 da = __ldcs(d4 + 2 * i);
        int4 db = __ldcs(d4 + 2 * i + 1);
        float2 a0 = __ldg(&g_tab[sa.x]), b0 = __ldg(&g_tab[da.x]);
        float2 a1 = __ldg(&g_tab[sa.y]), b1 = __ldg(&g_tab[da.y]);
        float2 a2 = __ldg(&g_tab[sa.z]), b2 = __ldg(&g_tab[da.z]);
        float2 a3 = __ldg(&g_tab[sa.w]), b3 = __ldg(&g_tab[da.w]);
        float2 a4 = __ldg(&g_tab[sb.x]), b4 = __ldg(&g_tab[db.x]);
        float2 a5 = __ldg(&g_tab[sb.y]), b5 = __ldg(&g_tab[db.y]);
        float2 a6 = __ldg(&g_tab[sb.z]), b6 = __ldg(&g_tab[db.z]);
        float2 a7 = __ldg(&g_tab[sb.w]), b7 = __ldg(&g_tab[db.w]);
        float q0 = edge_quad(a0, b0);
        float q1 = edge_quad(a1, b1);
        float q2 = edge_quad(a2, b2);
        float q3 = edge_quad(a3, b3);
        float q4 = edge_quad(a4, b4);
        float q5 = edge_quad(a5, b5);
        float q6 = edge_quad(a6, b6);
        float q7 = edge_quad(a7, b7);
        float h0 = __fadd_rn(__fadd_rn(q0, q1), __fadd_rn(q2, q3));
        float h1 = __fadd_rn(__fadd_rn(q4, q5), __fadd_rn(q6, q7));
        prox += (double)__fadd_rn(h0, h1);   // one DADD per 8 edges
    }
    for (long long e = (n8 << 3) + tid; e < n_edges; e += stride) {
        prox += (double)edge_quad(__ldg(&g_tab[src[e]]), __ldg(&g_tab[dst[e]]));
    }

    double bp = block_reduce_double(prox, s_red);
    if (threadIdx.x == 0) {
        g_part_prox[blockIdx.x] = bp;
        __threadfence();
        unsigned int t = atomicAdd(&g_done, 1u);
        s_last = (t == gridDim.x - 1) ? 1u : 0u;
    }
    __syncthreads();

    if (s_last) {
        double p = 0.0, c = 0.0;
        for (int i = threadIdx.x; i < gridDim.x; i += NTHR) p += g_part_prox[i];
        for (int i = threadIdx.x; i < n_comp_blocks; i += NTHR) c += g_part_comp[i];
        p = block_reduce_double(p, s_red);
        __syncthreads();
        c = block_reduce_double(c, s_red);
        if (threadIdx.x == 0) { s_pc[0] = p; s_pc[1] = c; }
        __syncthreads();

        if (threadIdx.x < 32) {
            int n_sp = (int)((n_edges < 10) ? n_edges : 10);
            double q = 0.0;
            if (threadIdx.x < n_sp) {
                float2 a = g_tab[src[threadIdx.x]];
                float2 b = g_tab[dst[threadIdx.x]];
                // lines: cross([x,y,1],[0,0,1]) = (y, -x, 0); time = 0
                float aa  = -__fadd_rn(__fmul_rn(a.y, a.y), __fmul_rn(a.x, a.x));
                float bb  = -__fadd_rn(__fmul_rn(b.y, b.y), __fmul_rn(b.x, b.x));
                float ab  = -__fadd_rn(__fmul_rn(a.y, b.y), __fmul_rn(a.x, b.x));
                float den = __fmul_rn(aa, bb);
                float num = __fsub_rn(__fmul_rn(ab, ab), den);
                q = (double)ref_safe_div(num, den);
            }
            #pragma unroll
            for (int o = 16; o; o >>= 1) q += __shfl_down_sync(0xffffffffu, q, o);
            if (threadIdx.x == 0) {
                double prox_m = s_pc[0] / (double)n_edges;
                double comp_m = s_pc[1] / (double)n_nodes;
                double spr_m  = q / (double)n_sp;
                out[0] = (float)((prox_m + comp_m) + 0.1 * spr_m);
                g_done = 0u;   // reset for next graph replay
            }
        }
    }
}

// ---------------------------------------------------------------------------
extern "C" void kernel_launch(void* const* d_in, const int* in_sizes, int n_in,
                              void* d_out, int out_size) {
    const float* z  = (const float*)d_in[0];
    const int*   ei = (const int*)d_in[1];

    int       n_nodes = in_sizes[0] / DIM;
    long long n_edges = (long long)in_sizes[1] / 2;
    const int* src = ei;
    const int* dst = ei + n_edges;

    int nba = (n_nodes + NTHR - 1) / NTHR;
    node_kernel<<<nba, NTHR>>>(z, n_nodes);
    edge_kernel<<<EBLK, NTHR>>>(src, dst, n_edges, n_nodes, nba, (float*)d_out);
}